// round 11
// baseline (speedup 1.0000x reference)
#include <cuda_runtime.h>
#include <cstdint>

#define BQ    64
#define DIMS  256
#define RDEG  32
#define EF    32
#define KOUT  10
#define NPTS  100000
#define VIS_WORDS ((NPTS + 31) / 32)   // 3125

typedef unsigned long long u64;

__device__ __forceinline__ u64 shfl_xor64(u64 v, int m) {
    return __shfl_xor_sync(0xffffffffu, v, m);
}
__device__ __forceinline__ u64 u64min(u64 a, u64 b) { return a < b ? a : b; }
__device__ __forceinline__ u64 u64max(u64 a, u64 b) { return a > b ? a : b; }

#define BSTAGE(v, kk, jj) {                                        \
    u64 _o = shfl_xor64(v, jj);                                    \
    bool _up    = ((lane & (kk)) == 0);                            \
    bool _lower = ((lane & (jj)) == 0);                            \
    v = (_up == _lower) ? u64min(v, _o) : u64max(v, _o); }

// Full ascending bitonic sort of 32 u64 keys (one per lane), 15 stages.
#define SORT32(v) {                                                \
    BSTAGE(v, 2, 1);                                               \
    BSTAGE(v, 4, 2);  BSTAGE(v, 4, 1);                             \
    BSTAGE(v, 8, 4);  BSTAGE(v, 8, 2);  BSTAGE(v, 8, 1);           \
    BSTAGE(v, 16, 8); BSTAGE(v, 16, 4); BSTAGE(v, 16, 2); BSTAGE(v, 16, 1); \
    BSTAGE(v, 32, 16);BSTAGE(v, 32, 8); BSTAGE(v, 32, 4); BSTAGE(v, 32, 2); BSTAGE(v, 32, 1); }

// Warp-collective squared distance (binary-tree fp32 sum, matches XLA tree reduce).
__device__ __forceinline__ float warp_sqdist(const float* __restrict__ storage,
                                             int id, float4 b0, float4 b1, int lane) {
    const float4* row = (const float4*)(storage + (size_t)id * DIMS);
    float4 a0 = row[lane], a1 = row[lane + 32];
    float d0 = a0.x - b0.x, d1 = a0.y - b0.y, d2 = a0.z - b0.z, d3 = a0.w - b0.w;
    float e0 = a1.x - b1.x, e1 = a1.y - b1.y, e2 = a1.z - b1.z, e3 = a1.w - b1.w;
    float s = ((d0 * d0 + d1 * d1) + (d2 * d2 + d3 * d3))
            + ((e0 * e0 + e1 * e1) + (e2 * e2 + e3 * e3));
#pragma unroll
    for (int o = 16; o; o >>= 1) s += __shfl_xor_sync(0xffffffffu, s, o);
    return s;
}

// Two distances, loads issued up-front (dual-duty worker warps).
__device__ __forceinline__ void warp_sqdist2(const float* __restrict__ storage,
                                             int idA, int idB, bool cA, bool cB,
                                             float4 q0, float4 q1, int lane,
                                             float& sA, float& sB) {
    float4 z = make_float4(0.f, 0.f, 0.f, 0.f);
    float4 a0 = z, a1 = z, b0 = z, b1 = z;
    if (cA) { const float4* r = (const float4*)(storage + (size_t)idA * DIMS);
              a0 = r[lane]; a1 = r[lane + 32]; }
    if (cB) { const float4* r = (const float4*)(storage + (size_t)idB * DIMS);
              b0 = r[lane]; b1 = r[lane + 32]; }
    float d0 = a0.x - q0.x, d1 = a0.y - q0.y, d2 = a0.z - q0.z, d3 = a0.w - q0.w;
    float e0 = a1.x - q1.x, e1 = a1.y - q1.y, e2 = a1.z - q1.z, e3 = a1.w - q1.w;
    float f0 = b0.x - q0.x, f1 = b0.y - q0.y, f2 = b0.z - q0.z, f3 = b0.w - q0.w;
    float g0 = b1.x - q1.x, g1 = b1.y - q1.y, g2 = b1.z - q1.z, g3 = b1.w - q1.w;
    float x = ((d0*d0 + d1*d1) + (d2*d2 + d3*d3)) + ((e0*e0 + e1*e1) + (e2*e2 + e3*e3));
    float y = ((f0*f0 + f1*f1) + (f2*f2 + f3*f3)) + ((g0*g0 + g1*g1) + (g2*g2 + g3*g3));
#pragma unroll
    for (int o = 16; o; o >>= 1) {
        x += __shfl_xor_sync(0xffffffffu, x, o);
        y += __shfl_xor_sync(0xffffffffu, y, o);
    }
    sA = x; sB = y;
}

__global__ __launch_bounds__(1024, 1)
void nsw_search_kernel(const float* __restrict__ query,
                       const float* __restrict__ storage,
                       const int*   __restrict__ graph,
                       const int*   __restrict__ initial,
                       float*       __restrict__ out) {
    __shared__ unsigned int vis[VIS_WORDS];      // visited bitset (warp0-owned after init)
    __shared__ int          nbid[2][RDEG];       // neighbor ids, parity double-buffered
    __shared__ unsigned int freshm[2][RDEG];     // freshness, parity double-buffered
    __shared__ unsigned int ndb[RDEG];           // neighbor dist bits
    __shared__ u64          skb[RDEG];           // sorted neighbor keys (warp1 -> warp0)
    __shared__ int          initids[EF];
    __shared__ unsigned int initdb[EF];

    const int b    = blockIdx.x;
    const int tid  = threadIdx.x;
    const int w    = tid >> 5;
    const int lane = tid & 31;
    const unsigned int INFB = __float_as_uint(1e30f);

    const float4* qrow = (const float4*)(query + (size_t)b * DIMS);
    const float4 q0 = qrow[lane], q1 = qrow[lane + 32];

    // ---- init ----
    for (int i = tid; i < VIS_WORDS; i += 1024) vis[i] = 0u;
    if (w == 0) initids[lane] = __ldg(initial + b * EF + lane);
    __syncthreads();

    // initial candidate distances (warp w -> initids[w]); warp 1 marks visited;
    // warp 2 L2-warms init graph rows (1 line each).
    {
        float s = warp_sqdist(storage, initids[w], q0, q1, lane);
        if (lane == 0) initdb[w] = __float_as_uint(s);
    }
    if (w == 1) {
        int id = initids[lane];
        atomicOr(&vis[id >> 5], 1u << (id & 31));        // visited[init] = True
    }
    if (w == 2) {
        asm volatile("prefetch.global.L2 [%0];"
                     :: "l"(graph + (size_t)initids[lane] * RDEG));
    }
    __syncthreads();

    // ---- bootstrap (warp 0 does everything, as in R8) ----
    u64 ka = 0;   // sorted pool key (lives in warp 0): dist(32)|rank(6)@25|id(17)@1|exp(1)@0
    if (w == 0) {
        ka = ((u64)initdb[lane] << 32) | ((u64)(unsigned)lane << 25)
           | ((u64)(unsigned)initids[lane] << 1);
        u64 mk = ka;
#pragma unroll
        for (int o = 16; o; o >>= 1) mk = u64min(mk, shfl_xor64(mk, o));
        const int u  = (int)((mk >> 1) & 0x1FFFFu);
        const int nb = __ldg(graph + (size_t)u * RDEG + lane);   // overlaps the sort
        SORT32(ka);
        {   // rebuild: slot = sorted rank; exp for id == u
            unsigned int d = (unsigned int)(ka >> 32);
            int id = (int)((ka >> 1) & 0x1FFFFu);
            unsigned int e = (id == u) ? 1u : 0u;
            ka = ((u64)d << 32) | ((u64)(unsigned)lane << 25) | ((u64)(unsigned)id << 1) | e;
        }
        {   // storage prefetch for step-0 neighbors
            const float* rp = storage + (size_t)nb * DIMS;
#pragma unroll
            for (int i = 0; i < 8; i++)
                asm volatile("prefetch.global.L2 [%0];" :: "l"(rp + i * 32));
        }
        // freshness reads for ALL neighbors before any visited write
        unsigned int word  = vis[nb >> 5];
        unsigned int fresh = ((word >> (nb & 31)) & 1u) ^ 1u;
        __syncwarp();
        nbid[0][lane]   = nb;
        freshm[0][lane] = fresh;
        atomicOr(&vis[nb >> 5], 1u << (nb & 31));
    }
    __syncthreads();

    int u_reg = 0;   // warp 0: node picked in the previous phase B (exp-marked at merge)

    // ---- ef_search expansion steps ----
    for (int t = 0; t < EF; ++t) {
        const int par = t & 1;

        // ===== Phase A: workers (warps 2..31) dist N_t; warp 0 merges N_{t-1} =====
        if (w >= 2) {
            const int  n1   = w - 2;            // neighbors 0..29
            const bool dual = (w >= 30);        // warps 30,31 also take 30,31
            const int  n2   = w;
            int      idA = nbid[par][n1];
            unsigned fA  = freshm[par][n1];
            int      idB = dual ? nbid[par][n2] : 0;
            unsigned fB  = dual ? freshm[par][n2] : 0u;
            if (lane == 0) {   // L2-warm candidate next-u graph rows
                asm volatile("prefetch.global.L2 [%0];"
                             :: "l"(graph + (size_t)idA * RDEG));
                if (dual)
                    asm volatile("prefetch.global.L2 [%0];"
                                 :: "l"(graph + (size_t)idB * RDEG));
            }
            unsigned rA = INFB, rB = INFB;
            if (!dual) {
                if (fA) rA = __float_as_uint(warp_sqdist(storage, idA, q0, q1, lane));
            } else {
                float sA, sB;
                warp_sqdist2(storage, idA, idB, fA != 0u, fB != 0u, q0, q1, lane, sA, sB);
                if (fA) rA = __float_as_uint(sA);
                if (fB) rB = __float_as_uint(sB);
            }
            if (lane == 0) { ndb[n1] = rA; if (dual) ndb[n2] = rB; }
        } else if (w == 0 && t > 0) {
            // deferred merge of step t-1: top-32 of (P_{t-1} asc) ∪ (skb asc)
            u64 lo = u64min(ka, skb[lane ^ 31]);
#pragma unroll
            for (int j = 16; j >= 1; j >>= 1) {
                u64 o = shfl_xor64(lo, j);
                lo = ((lane & j) == 0) ? u64min(lo, o) : u64max(lo, o);
            }
            {   // rebuild sorted pool: slot = rank; exp |= (id == u_reg)
                unsigned int d = (unsigned int)(lo >> 32);
                int id = (int)((lo >> 1) & 0x1FFFFu);
                unsigned int e = (unsigned int)(lo & 1ull);
                if (id == u_reg) e = 1u;
                ka = ((u64)d << 32) | ((u64)(unsigned)lane << 25)
                   | ((u64)(unsigned)id << 1) | e;
            }
        }
        __syncthreads();

        // ===== Phase B: warp 0 pre-picks u_{t+1} + publishes; warp 1 sorts N_t =====
        const bool more = (t < EF - 1);
        if (w == 0) {
            if (more) {
                u64 kb = ((u64)ndb[lane] << 32) | ((u64)(unsigned)(lane + 32) << 25)
                       | ((u64)(unsigned)nbid[par][lane] << 1);
                // min-key unexpanded over (P_t ∪ N_t) always survives the merge
                u64 mk = u64min((ka & 1ull) ? ~0ull : ka, kb);
#pragma unroll
                for (int o = 16; o; o >>= 1) mk = u64min(mk, shfl_xor64(mk, o));
                u_reg = (int)((mk >> 1) & 0x1FFFFu);
                int nb = __ldg(graph + (size_t)u_reg * RDEG + lane);  // L2-hot
                {   // storage prefetch: lead = rest of sort + sync + dist start
                    const float* rp = storage + (size_t)nb * DIMS;
#pragma unroll
                    for (int i = 0; i < 8; i++)
                        asm volatile("prefetch.global.L2 [%0];" :: "l"(rp + i * 32));
                }
                // freshness reads before any visited write
                unsigned int word  = vis[nb >> 5];
                unsigned int fresh = ((word >> (nb & 31)) & 1u) ^ 1u;
                __syncwarp();
                nbid[par ^ 1][lane]   = nb;
                freshm[par ^ 1][lane] = fresh;
                atomicOr(&vis[nb >> 5], 1u << (nb & 31));
            }
        } else if (w == 1) {
            u64 kb = ((u64)ndb[lane] << 32) | ((u64)(unsigned)(lane + 32) << 25)
                   | ((u64)(unsigned)nbid[par][lane] << 1);      // exp = 0
            SORT32(kb);
            skb[lane] = kb;
        }
        __syncthreads();
    }

    // ---- final merge of step EF-1, then output top-10 ----
    if (w == 0) {
        u64 lo = u64min(ka, skb[lane ^ 31]);
#pragma unroll
        for (int j = 16; j >= 1; j >>= 1) {
            u64 o = shfl_xor64(lo, j);
            lo = ((lane & j) == 0) ? u64min(lo, o) : u64max(lo, o);
        }
        // Tuple outputs flattened+concatenated: ids[B*K] then dists[B*K], float32.
        if (lane < KOUT) {
            out[b * KOUT + lane]             = (float)((lo >> 1) & 0x1FFFFu);
            out[BQ * KOUT + b * KOUT + lane] = __uint_as_float((unsigned int)(lo >> 32));
        }
    }
}

extern "C" void kernel_launch(void* const* d_in, const int* in_sizes, int n_in,
                              void* d_out, int out_size) {
    const float* query   = (const float*)d_in[0];
    const float* storage = (const float*)d_in[1];
    const int*   graph   = (const int*)d_in[2];
    const int*   initial = (const int*)d_in[3];
    (void)in_sizes; (void)n_in; (void)out_size;
    nsw_search_kernel<<<BQ, 1024>>>(query, storage, graph, initial, (float*)d_out);
}

// round 12
// speedup vs baseline: 1.7593x; 1.7593x over previous
#include <cuda_runtime.h>
#include <cstdint>

#define BQ    64
#define DIMS  256
#define RDEG  32
#define EF    32
#define KOUT  10
#define NPTS  100000
#define VIS_WORDS ((NPTS + 31) / 32)   // 3125

typedef unsigned long long u64;

__device__ __forceinline__ u64 shfl_xor64(u64 v, int m) {
    return __shfl_xor_sync(0xffffffffu, v, m);
}
__device__ __forceinline__ u64 u64min(u64 a, u64 b) { return a < b ? a : b; }
__device__ __forceinline__ u64 u64max(u64 a, u64 b) { return a > b ? a : b; }

// Rank of this lane's key among all 32 lanes' keys (keys unique -> exact
// sorted position). All 32 broadcasts are independent -> issue-bound, not
// latency-bound (vs the 15-stage bitonic dependency chain).
__device__ __forceinline__ int warp_rank32(u64 k) {
    int r0 = 0, r1 = 0, r2 = 0, r3 = 0;
#pragma unroll
    for (int j = 0; j < 32; j += 4) {
        u64 k0 = __shfl_sync(0xffffffffu, k, j + 0);
        u64 k1 = __shfl_sync(0xffffffffu, k, j + 1);
        u64 k2 = __shfl_sync(0xffffffffu, k, j + 2);
        u64 k3 = __shfl_sync(0xffffffffu, k, j + 3);
        r0 += (k0 < k); r1 += (k1 < k); r2 += (k2 < k); r3 += (k3 < k);
    }
    return (r0 + r1) + (r2 + r3);
}

// Warp-collective squared distance (binary-tree fp32 sum, matches XLA tree reduce).
__device__ __forceinline__ float warp_sqdist(const float* __restrict__ storage,
                                             int id, float4 b0, float4 b1, int lane) {
    const float4* row = (const float4*)(storage + (size_t)id * DIMS);
    float4 a0 = row[lane], a1 = row[lane + 32];
    float d0 = a0.x - b0.x, d1 = a0.y - b0.y, d2 = a0.z - b0.z, d3 = a0.w - b0.w;
    float e0 = a1.x - b1.x, e1 = a1.y - b1.y, e2 = a1.z - b1.z, e3 = a1.w - b1.w;
    float s = ((d0 * d0 + d1 * d1) + (d2 * d2 + d3 * d3))
            + ((e0 * e0 + e1 * e1) + (e2 * e2 + e3 * e3));
#pragma unroll
    for (int o = 16; o; o >>= 1) s += __shfl_xor_sync(0xffffffffu, s, o);
    return s;
}

__global__ __launch_bounds__(1024, 1)
void nsw_search_kernel(const float* __restrict__ query,
                       const float* __restrict__ storage,
                       const int*   __restrict__ graph,
                       const int*   __restrict__ initial,
                       float*       __restrict__ out) {
    __shared__ unsigned int vis[VIS_WORDS];      // visited bitset (warp0-owned after init)
    __shared__ int          nbid[2][RDEG];       // neighbor ids, parity double-buffered
    __shared__ unsigned int freshm[2][RDEG];     // freshness, parity double-buffered
    __shared__ unsigned int ndb[RDEG];           // neighbor dist bits
    __shared__ u64          skb[RDEG];           // sorted neighbor keys (warp1 -> warp0)
    __shared__ int          initids[EF];
    __shared__ unsigned int initdb[EF];

    const int b    = blockIdx.x;
    const int tid  = threadIdx.x;
    const int w    = tid >> 5;
    const int lane = tid & 31;
    const unsigned int INFB = __float_as_uint(1e30f);

    // Query vector lives in registers.
    const float4* qrow = (const float4*)(query + (size_t)b * DIMS);
    const float4 q0 = qrow[lane], q1 = qrow[lane + 32];

    // ---- init ----
    for (int i = tid; i < VIS_WORDS; i += 1024) vis[i] = 0u;
    if (w == 0) initids[lane] = __ldg(initial + b * EF + lane);
    __syncthreads();

    // initial candidate distances (warp w -> initids[w]); warp 1 marks visited;
    // warp 2 L2-warms all init graph rows (1 line each).
    {
        float s = warp_sqdist(storage, initids[w], q0, q1, lane);
        if (lane == 0) initdb[w] = __float_as_uint(s);
    }
    if (w == 1) {
        int id = initids[lane];
        atomicOr(&vis[id >> 5], 1u << (id & 31));        // visited[init] = True
    }
    if (w == 2) {
        asm volatile("prefetch.global.L2 [%0];"
                     :: "l"(graph + (size_t)initids[lane] * RDEG));
    }
    __syncthreads();

    u64 ka = 0;   // sorted candidate pool key: dist(32)|slot(6)@25|id(17)@1|exp(1)@0
    if (w == 0) {
        // keys from the (unsorted) initial pool; slot = original index (stability)
        ka = ((u64)initdb[lane] << 32) | ((u64)(unsigned)lane << 25)
           | ((u64)(unsigned)initids[lane] << 1);
        // pick u0 = argmin (all unexpanded); graph LDG overlaps the rank sort
        u64 mk = ka;
#pragma unroll
        for (int o = 16; o; o >>= 1) mk = u64min(mk, shfl_xor64(mk, o));
        const int u  = (int)((mk >> 1) & 0x1FFFFu);
        const int nb = __ldg(graph + (size_t)u * RDEG + lane);
        // rank sort via smem scratch
        {
            int rank = warp_rank32(ka);
            skb[rank] = ka;
            __syncwarp();
            ka = skb[lane];
        }
        {   // rebuild: slot = sorted rank; exp for id == u
            unsigned int d = (unsigned int)(ka >> 32);
            int id = (int)((ka >> 1) & 0x1FFFFu);
            unsigned int e = (id == u) ? 1u : 0u;
            ka = ((u64)d << 32) | ((u64)(unsigned)lane << 25) | ((u64)(unsigned)id << 1) | e;
        }
        {   // storage prefetch for step-0 neighbors
            const float* rp = storage + (size_t)nb * DIMS;
#pragma unroll
            for (int i = 0; i < 8; i++)
                asm volatile("prefetch.global.L2 [%0];" :: "l"(rp + i * 32));
        }
        // freshness reads for ALL neighbors before any visited write
        unsigned int word  = vis[nb >> 5];
        unsigned int fresh = ((word >> (nb & 31)) & 1u) ^ 1u;
        __syncwarp();
        nbid[0][lane]   = nb;
        freshm[0][lane] = fresh;
        atomicOr(&vis[nb >> 5], 1u << (nb & 31));
    }
    __syncthreads();

    // ---- ef_search expansion steps; pool stays sorted (== top_k order)
    for (int t = 0; t < EF; ++t) {
        const int par = t & 1;

        // Phase 2 (all 32 warps): warp w computes distance to neighbor w.
        // Lane 0 also L2-warms that node's graph row (candidate next-u).
        {
            int      idA = nbid[par][w];
            unsigned fA  = freshm[par][w];
            if (lane == 0)
                asm volatile("prefetch.global.L2 [%0];"
                             :: "l"(graph + (size_t)idA * RDEG));
            unsigned int res = INFB;
            if (fA) {
                float s = warp_sqdist(storage, idA, q0, q1, lane);
                res = __float_as_uint(s);
            }
            if (lane == 0) ndb[w] = res;
        }
        __syncthreads();

        const bool more = (t < EF - 1);

        if (w == 1) {
            // ---- sort path: rank-sort the 32 neighbor keys straight into smem ----
            u64 kb = ((u64)ndb[lane] << 32) | ((u64)(unsigned)(lane + 32) << 25)
                   | ((u64)(unsigned)nbid[par][lane] << 1);      // exp = 0
            int rank = warp_rank32(kb);
            skb[rank] = kb;
            asm volatile("bar.sync 3, 64;" ::: "memory");        // meet warp 0
        } else if (w == 0) {
            // ---- pick path ----
            int u = 0, nb = 0;
            if (more) {
                u64 kb = ((u64)ndb[lane] << 32) | ((u64)(unsigned)(lane + 32) << 25)
                       | ((u64)(unsigned)nbid[par][lane] << 1);
                // min-key unexpanded always survives into the top-32 -> safe pre-pick
                u64 mk = u64min((ka & 1ull) ? ~0ull : ka, kb);
#pragma unroll
                for (int o = 16; o; o >>= 1) mk = u64min(mk, shfl_xor64(mk, o));
                u  = (int)((mk >> 1) & 0x1FFFFu);
                nb = __ldg(graph + (size_t)u * RDEG + lane);     // L2-hot; waits under bar3
            }
            asm volatile("bar.sync 3, 64;" ::: "memory");        // sorted keys ready

            if (more) {
                // storage prefetch: depends only on nb (just landed) — issues now,
                // merge ALU below runs over the prefetch traffic.
                const float* rp = storage + (size_t)nb * DIMS;
#pragma unroll
                for (int i = 0; i < 8; i++)
                    asm volatile("prefetch.global.L2 [%0];" :: "l"(rp + i * 32));
            }

            // top-32 of two ascending 32-seqs: min vs reversed (direct smem index),
            // then 5-stage bitonic cleanup.
            u64 lo = u64min(ka, skb[lane ^ 31]);
#pragma unroll
            for (int j = 16; j >= 1; j >>= 1) {
                u64 o = shfl_xor64(lo, j);
                lo = ((lane & j) == 0) ? u64min(lo, o) : u64max(lo, o);
            }
            {   // rebuild sorted pool: slot = rank; mark exp for id == u_next
                unsigned int d = (unsigned int)(lo >> 32);
                int id = (int)((lo >> 1) & 0x1FFFFu);
                unsigned int e = (unsigned int)(lo & 1ull);
                if (more && id == u) e = 1u;
                ka = ((u64)d << 32) | ((u64)(unsigned)lane << 25)
                   | ((u64)(unsigned)id << 1) | e;
            }

            if (more) {
                // freshness reads before any visited write (vis is warp0-private now)
                unsigned int word  = vis[nb >> 5];
                unsigned int fresh = ((word >> (nb & 31)) & 1u) ^ 1u;
                __syncwarp();
                nbid[par ^ 1][lane]   = nb;
                freshm[par ^ 1][lane] = fresh;
                atomicOr(&vis[nb >> 5], 1u << (nb & 31));
            }
        }
        __syncthreads();
    }

    // ---- output: final top_k(-cd, 10) == first 10 of the sorted pool ----
    // Tuple outputs flattened+concatenated: ids[B*K] then dists[B*K], as float32.
    if (w == 0 && lane < KOUT) {
        out[b * KOUT + lane]             = (float)((ka >> 1) & 0x1FFFFu);
        out[BQ * KOUT + b * KOUT + lane] = __uint_as_float((unsigned int)(ka >> 32));
    }
}

extern "C" void kernel_launch(void* const* d_in, const int* in_sizes, int n_in,
                              void* d_out, int out_size) {
    const float* query   = (const float*)d_in[0];
    const float* storage = (const float*)d_in[1];
    const int*   graph   = (const int*)d_in[2];
    const int*   initial = (const int*)d_in[3];
    (void)in_sizes; (void)n_in; (void)out_size;
    nsw_search_kernel<<<BQ, 1024>>>(query, storage, graph, initial, (float*)d_out);
}

// round 13
// speedup vs baseline: 1.7994x; 1.0227x over previous
#include <cuda_runtime.h>
#include <cstdint>

#define BQ    64
#define DIMS  256
#define RDEG  32
#define EF    32
#define KOUT  10
#define NPTS  100000
#define VIS_WORDS ((NPTS + 31) / 32)   // 3125

typedef unsigned long long u64;

__device__ __forceinline__ u64 shfl_xor64(u64 v, int m) {
    return __shfl_xor_sync(0xffffffffu, v, m);
}
__device__ __forceinline__ u64 u64min(u64 a, u64 b) { return a < b ? a : b; }
__device__ __forceinline__ u64 u64max(u64 a, u64 b) { return a > b ? a : b; }

// L1 prefetch: the consumer warps live on the SAME SM (one CTA = one query),
// so filling L1 (~40cyc hit) beats L2 (~250cyc hit).
#define PF_L1(p) asm volatile("prefetch.global.L1 [%0];" :: "l"(p))

// Rank of this lane's key among all 32 lanes' keys (keys unique -> exact
// sorted position). All 32 broadcasts are independent -> issue-bound.
__device__ __forceinline__ int warp_rank32(u64 k) {
    int r0 = 0, r1 = 0, r2 = 0, r3 = 0;
#pragma unroll
    for (int j = 0; j < 32; j += 4) {
        u64 k0 = __shfl_sync(0xffffffffu, k, j + 0);
        u64 k1 = __shfl_sync(0xffffffffu, k, j + 1);
        u64 k2 = __shfl_sync(0xffffffffu, k, j + 2);
        u64 k3 = __shfl_sync(0xffffffffu, k, j + 3);
        r0 += (k0 < k); r1 += (k1 < k); r2 += (k2 < k); r3 += (k3 < k);
    }
    return (r0 + r1) + (r2 + r3);
}

// Warp-collective squared distance (binary-tree fp32 sum, matches XLA tree reduce).
__device__ __forceinline__ float warp_sqdist(const float* __restrict__ storage,
                                             int id, float4 b0, float4 b1, int lane) {
    const float4* row = (const float4*)(storage + (size_t)id * DIMS);
    float4 a0 = row[lane], a1 = row[lane + 32];
    float d0 = a0.x - b0.x, d1 = a0.y - b0.y, d2 = a0.z - b0.z, d3 = a0.w - b0.w;
    float e0 = a1.x - b1.x, e1 = a1.y - b1.y, e2 = a1.z - b1.z, e3 = a1.w - b1.w;
    float s = ((d0 * d0 + d1 * d1) + (d2 * d2 + d3 * d3))
            + ((e0 * e0 + e1 * e1) + (e2 * e2 + e3 * e3));
#pragma unroll
    for (int o = 16; o; o >>= 1) s += __shfl_xor_sync(0xffffffffu, s, o);
    return s;
}

__global__ __launch_bounds__(1024, 1)
void nsw_search_kernel(const float* __restrict__ query,
                       const float* __restrict__ storage,
                       const int*   __restrict__ graph,
                       const int*   __restrict__ initial,
                       float*       __restrict__ out) {
    __shared__ unsigned int vis[VIS_WORDS];      // visited bitset (warp0-owned after init)
    __shared__ int          nbid[2][RDEG];       // neighbor ids, parity double-buffered
    __shared__ unsigned int freshm[2][RDEG];     // freshness, parity double-buffered
    __shared__ unsigned int ndb[RDEG];           // neighbor dist bits
    __shared__ u64          skb[RDEG];           // sorted neighbor keys (warp1 -> warp0)
    __shared__ int          initids[EF];
    __shared__ unsigned int initdb[EF];

    const int b    = blockIdx.x;
    const int tid  = threadIdx.x;
    const int w    = tid >> 5;
    const int lane = tid & 31;
    const unsigned int INFB = __float_as_uint(1e30f);

    // Query vector lives in registers.
    const float4* qrow = (const float4*)(query + (size_t)b * DIMS);
    const float4 q0 = qrow[lane], q1 = qrow[lane + 32];

    // ---- init ----
    for (int i = tid; i < VIS_WORDS; i += 1024) vis[i] = 0u;
    if (w == 0) initids[lane] = __ldg(initial + b * EF + lane);
    __syncthreads();

    // initial candidate distances (warp w -> initids[w]); warp 1 marks visited;
    // warp 2 L1-warms all init graph rows (1 line each).
    {
        float s = warp_sqdist(storage, initids[w], q0, q1, lane);
        if (lane == 0) initdb[w] = __float_as_uint(s);
    }
    if (w == 1) {
        int id = initids[lane];
        atomicOr(&vis[id >> 5], 1u << (id & 31));        // visited[init] = True
    }
    if (w == 2) {
        PF_L1(graph + (size_t)initids[lane] * RDEG);
    }
    __syncthreads();

    u64 ka = 0;   // sorted candidate pool key: dist(32)|slot(6)@25|id(17)@1|exp(1)@0
    if (w == 0) {
        // keys from the (unsorted) initial pool; slot = original index (stability)
        ka = ((u64)initdb[lane] << 32) | ((u64)(unsigned)lane << 25)
           | ((u64)(unsigned)initids[lane] << 1);
        // pick u0 = argmin (all unexpanded); graph LDG overlaps the rank sort
        u64 mk = ka;
#pragma unroll
        for (int o = 16; o; o >>= 1) mk = u64min(mk, shfl_xor64(mk, o));
        const int u  = (int)((mk >> 1) & 0x1FFFFu);
        const int nb = __ldg(graph + (size_t)u * RDEG + lane);
        // rank sort via smem scratch
        {
            int rank = warp_rank32(ka);
            skb[rank] = ka;
            __syncwarp();
            ka = skb[lane];
        }
        {   // rebuild: slot = sorted rank; exp for id == u
            unsigned int d = (unsigned int)(ka >> 32);
            int id = (int)((ka >> 1) & 0x1FFFFu);
            unsigned int e = (id == u) ? 1u : 0u;
            ka = ((u64)d << 32) | ((u64)(unsigned)lane << 25) | ((u64)(unsigned)id << 1) | e;
        }
        {   // L1 storage prefetch for step-0 neighbors
            const float* rp = storage + (size_t)nb * DIMS;
#pragma unroll
            for (int i = 0; i < 8; i++) PF_L1(rp + i * 32);
        }
        // freshness reads for ALL neighbors before any visited write
        unsigned int word  = vis[nb >> 5];
        unsigned int fresh = ((word >> (nb & 31)) & 1u) ^ 1u;
        __syncwarp();
        nbid[0][lane]   = nb;
        freshm[0][lane] = fresh;
        atomicOr(&vis[nb >> 5], 1u << (nb & 31));
    }
    __syncthreads();

    // ---- ef_search expansion steps; pool stays sorted (== top_k order)
    for (int t = 0; t < EF; ++t) {
        const int par = t & 1;

        // Phase 2 (all 32 warps): warp w computes distance to neighbor w.
        // Lane 0 also L1-warms that node's graph row (candidate next-u).
        {
            int      idA = nbid[par][w];
            unsigned fA  = freshm[par][w];
            if (lane == 0) PF_L1(graph + (size_t)idA * RDEG);
            unsigned int res = INFB;
            if (fA) {
                float s = warp_sqdist(storage, idA, q0, q1, lane);
                res = __float_as_uint(s);
            }
            if (lane == 0) ndb[w] = res;
        }
        __syncthreads();

        const bool more = (t < EF - 1);

        if (w == 1) {
            // ---- sort path: rank-sort the 32 neighbor keys straight into smem ----
            u64 kb = ((u64)ndb[lane] << 32) | ((u64)(unsigned)(lane + 32) << 25)
                   | ((u64)(unsigned)nbid[par][lane] << 1);      // exp = 0
            int rank = warp_rank32(kb);
            skb[rank] = kb;
            asm volatile("bar.sync 3, 64;" ::: "memory");        // meet warp 0
        } else if (w == 0) {
            // ---- pick path ----
            int u = 0, nb = 0;
            if (more) {
                u64 kb = ((u64)ndb[lane] << 32) | ((u64)(unsigned)(lane + 32) << 25)
                       | ((u64)(unsigned)nbid[par][lane] << 1);
                // min-key unexpanded always survives into the top-32 -> safe pre-pick
                u64 mk = u64min((ka & 1ull) ? ~0ull : ka, kb);
#pragma unroll
                for (int o = 16; o; o >>= 1) mk = u64min(mk, shfl_xor64(mk, o));
                u  = (int)((mk >> 1) & 0x1FFFFu);
                nb = __ldg(graph + (size_t)u * RDEG + lane);     // L1-hot; waits under bar3
            }
            asm volatile("bar.sync 3, 64;" ::: "memory");        // sorted keys ready

            if (more) {
                // L1 storage prefetch: depends only on nb (just landed) — issues now,
                // merge ALU below runs over the fill traffic.
                const float* rp = storage + (size_t)nb * DIMS;
#pragma unroll
                for (int i = 0; i < 8; i++) PF_L1(rp + i * 32);
            }

            // top-32 of two ascending 32-seqs: min vs reversed (direct smem index),
            // then 5-stage bitonic cleanup.
            u64 lo = u64min(ka, skb[lane ^ 31]);
#pragma unroll
            for (int j = 16; j >= 1; j >>= 1) {
                u64 o = shfl_xor64(lo, j);
                lo = ((lane & j) == 0) ? u64min(lo, o) : u64max(lo, o);
            }
            {   // rebuild sorted pool: slot = rank; mark exp for id == u_next
                unsigned int d = (unsigned int)(lo >> 32);
                int id = (int)((lo >> 1) & 0x1FFFFu);
                unsigned int e = (unsigned int)(lo & 1ull);
                if (more && id == u) e = 1u;
                ka = ((u64)d << 32) | ((u64)(unsigned)lane << 25)
                   | ((u64)(unsigned)id << 1) | e;
            }

            if (more) {
                // freshness reads before any visited write (vis is warp0-private)
                unsigned int word  = vis[nb >> 5];
                unsigned int fresh = ((word >> (nb & 31)) & 1u) ^ 1u;
                __syncwarp();
                nbid[par ^ 1][lane]   = nb;
                freshm[par ^ 1][lane] = fresh;
                atomicOr(&vis[nb >> 5], 1u << (nb & 31));
            }
        }
        __syncthreads();
    }

    // ---- output: final top_k(-cd, 10) == first 10 of the sorted pool ----
    // Tuple outputs flattened+concatenated: ids[B*K] then dists[B*K], as float32.
    if (w == 0 && lane < KOUT) {
        out[b * KOUT + lane]             = (float)((ka >> 1) & 0x1FFFFu);
        out[BQ * KOUT + b * KOUT + lane] = __uint_as_float((unsigned int)(ka >> 32));
    }
}

extern "C" void kernel_launch(void* const* d_in, const int* in_sizes, int n_in,
                              void* d_out, int out_size) {
    const float* query   = (const float*)d_in[0];
    const float* storage = (const float*)d_in[1];
    const int*   graph   = (const int*)d_in[2];
    const int*   initial = (const int*)d_in[3];
    (void)in_sizes; (void)n_in; (void)out_size;
    nsw_search_kernel<<<BQ, 1024>>>(query, storage, graph, initial, (float*)d_out);
}

// round 14
// speedup vs baseline: 2.1196x; 1.1780x over previous
#include <cuda_runtime.h>
#include <cstdint>

#define BQ    64
#define DIMS  256
#define RDEG  32
#define EF    32
#define KOUT  10
#define NPTS  100000
#define VIS_WORDS ((NPTS + 31) / 32)   // 3125

typedef unsigned long long u64;

__device__ __forceinline__ u64 shfl_xor64(u64 v, int m) {
    return __shfl_xor_sync(0xffffffffu, v, m);
}
__device__ __forceinline__ u64 u64min(u64 a, u64 b) { return a < b ? a : b; }
__device__ __forceinline__ u64 u64max(u64 a, u64 b) { return a > b ? a : b; }

#define PF_L1(p) asm volatile("prefetch.global.L1 [%0];" :: "l"(p))

// Rank of this lane's key among all 32 lanes' keys (keys unique -> exact
// sorted position). All 32 broadcasts are independent -> issue-bound.
__device__ __forceinline__ int warp_rank32(u64 k) {
    int r0 = 0, r1 = 0, r2 = 0, r3 = 0;
#pragma unroll
    for (int j = 0; j < 32; j += 4) {
        u64 k0 = __shfl_sync(0xffffffffu, k, j + 0);
        u64 k1 = __shfl_sync(0xffffffffu, k, j + 1);
        u64 k2 = __shfl_sync(0xffffffffu, k, j + 2);
        u64 k3 = __shfl_sync(0xffffffffu, k, j + 3);
        r0 += (k0 < k); r1 += (k1 < k); r2 += (k2 < k); r3 += (k3 < k);
    }
    return (r0 + r1) + (r2 + r3);
}

// Min key over the warp via two u32 REDUX ops (shallower than 5 chained shfl64).
// Returns the low 32 bits of the min key (which carry id<<1|exp).
__device__ __forceinline__ unsigned warp_min_key_lo(u64 mk) {
    unsigned hi  = (unsigned)(mk >> 32);
    unsigned mhi = __reduce_min_sync(0xffffffffu, hi);
    unsigned cl  = (hi == mhi) ? (unsigned)mk : 0xFFFFFFFFu;
    return __reduce_min_sync(0xffffffffu, cl);
}

// Warp-collective squared distance (binary-tree fp32 sum, matches XLA tree reduce).
__device__ __forceinline__ float warp_sqdist(const float* __restrict__ storage,
                                             int id, float4 b0, float4 b1, int lane) {
    const float4* row = (const float4*)(storage + (size_t)id * DIMS);
    float4 a0 = row[lane], a1 = row[lane + 32];
    float d0 = a0.x - b0.x, d1 = a0.y - b0.y, d2 = a0.z - b0.z, d3 = a0.w - b0.w;
    float e0 = a1.x - b1.x, e1 = a1.y - b1.y, e2 = a1.z - b1.z, e3 = a1.w - b1.w;
    float s = ((d0 * d0 + d1 * d1) + (d2 * d2 + d3 * d3))
            + ((e0 * e0 + e1 * e1) + (e2 * e2 + e3 * e3));
#pragma unroll
    for (int o = 16; o; o >>= 1) s += __shfl_xor_sync(0xffffffffu, s, o);
    return s;
}

__global__ __launch_bounds__(1024, 1)
void nsw_search_kernel(const float* __restrict__ query,
                       const float* __restrict__ storage,
                       const int*   __restrict__ graph,
                       const int*   __restrict__ initial,
                       float*       __restrict__ out) {
    __shared__ unsigned int vis[VIS_WORDS];      // visited bitset (warp0-owned after init)
    __shared__ int          nbid[2][RDEG];       // neighbor ids, parity double-buffered
    __shared__ unsigned int freshm[2][RDEG];     // freshness, parity double-buffered
    __shared__ unsigned int ndb[RDEG];           // neighbor dist bits
    __shared__ u64          skb[RDEG];           // sorted neighbor keys (warp1 -> warp0)
    __shared__ int          initids[EF];
    __shared__ unsigned int initdb[EF];

    const int b    = blockIdx.x;
    const int tid  = threadIdx.x;
    const int w    = tid >> 5;
    const int lane = tid & 31;
    const unsigned int INFB = __float_as_uint(1e30f);

    // Query vector lives in registers.
    const float4* qrow = (const float4*)(query + (size_t)b * DIMS);
    const float4 q0 = qrow[lane], q1 = qrow[lane + 32];

    // ---- init ----
    for (int i = tid; i < VIS_WORDS; i += 1024) vis[i] = 0u;
    if (w == 0) initids[lane] = __ldg(initial + b * EF + lane);
    __syncthreads();

    // initial candidate distances (warp w -> initids[w]); warp 1 marks visited;
    // warp 2 L1-warms all init graph rows (1 line each).
    {
        float s = warp_sqdist(storage, initids[w], q0, q1, lane);
        if (lane == 0) initdb[w] = __float_as_uint(s);
    }
    if (w == 1) {
        int id = initids[lane];
        atomicOr(&vis[id >> 5], 1u << (id & 31));        // visited[init] = True
    }
    if (w == 2) {
        PF_L1(graph + (size_t)initids[lane] * RDEG);
    }
    __syncthreads();

    u64 ka = 0;     // sorted pool key (warp 0): dist(32)|slot(6)@25|id(17)@1|exp(1)@0
    int u_reg = 0;  // warp 0: node picked last phase B; exp-marked at the deferred merge
    if (w == 0) {
        // keys from the (unsorted) initial pool; slot = original index (stability)
        ka = ((u64)initdb[lane] << 32) | ((u64)(unsigned)lane << 25)
           | ((u64)(unsigned)initids[lane] << 1);
        // pick u0 = argmin (all unexpanded) via REDUX; graph LDG overlaps the sort
        const int u  = (int)((warp_min_key_lo(ka) >> 1) & 0x1FFFFu);
        const int nb = __ldg(graph + (size_t)u * RDEG + lane);
        {   // rank sort via smem scratch
            int rank = warp_rank32(ka);
            skb[rank] = ka;
            __syncwarp();
            ka = skb[lane];
        }
        {   // rebuild: slot = sorted rank; exp for id == u
            unsigned int d = (unsigned int)(ka >> 32);
            int id = (int)((ka >> 1) & 0x1FFFFu);
            unsigned int e = (id == u) ? 1u : 0u;
            ka = ((u64)d << 32) | ((u64)(unsigned)lane << 25) | ((u64)(unsigned)id << 1) | e;
        }
        {   // L1 storage prefetch for step-0 neighbors
            const float* rp = storage + (size_t)nb * DIMS;
#pragma unroll
            for (int i = 0; i < 8; i++) PF_L1(rp + i * 32);
        }
        // freshness reads for ALL neighbors before any visited write
        unsigned int word  = vis[nb >> 5];
        unsigned int fresh = ((word >> (nb & 31)) & 1u) ^ 1u;
        __syncwarp();
        nbid[0][lane]   = nb;
        freshm[0][lane] = fresh;
        atomicOr(&vis[nb >> 5], 1u << (nb & 31));
    }
    __syncthreads();

    // ---- ef_search expansion steps ----
    for (int t = 0; t < EF; ++t) {
        const int par = t & 1;

        // ===== Phase A: all 32 warps dist(neighbor w); warp 0 also runs the
        // deferred merge of step t-1 inside its load shadow. =====
        {
            int      idA = nbid[par][w];
            unsigned fA  = freshm[par][w];
            if (lane == 0) PF_L1(graph + (size_t)idA * RDEG);
            const float4* row = (const float4*)(storage + (size_t)idA * DIMS);
            float4 a0, a1;
            const bool doload = (fA != 0u);
            if (doload) { a0 = row[lane]; a1 = row[lane + 32]; }   // issue loads

            if (w == 0 && t > 0) {
                // deferred merge: P_t = top32(P_{t-1} ∪ N_{t-1}); pure ALU + 1 LDS,
                // overlaps the outstanding distance loads.
                u64 lo = u64min(ka, skb[lane ^ 31]);
#pragma unroll
                for (int j = 16; j >= 1; j >>= 1) {
                    u64 o = shfl_xor64(lo, j);
                    lo = ((lane & j) == 0) ? u64min(lo, o) : u64max(lo, o);
                }
                unsigned int d = (unsigned int)(lo >> 32);
                int id = (int)((lo >> 1) & 0x1FFFFu);
                unsigned int e = (unsigned int)(lo & 1ull);
                if (id == u_reg) e = 1u;                // expand-mark last pick
                ka = ((u64)d << 32) | ((u64)(unsigned)lane << 25)
                   | ((u64)(unsigned)id << 1) | e;
            }

            unsigned int res = INFB;
            if (doload) {
                float d0 = a0.x - q0.x, d1 = a0.y - q0.y, d2 = a0.z - q0.z, d3 = a0.w - q0.w;
                float e0 = a1.x - q1.x, e1 = a1.y - q1.y, e2 = a1.z - q1.z, e3 = a1.w - q1.w;
                float s = ((d0 * d0 + d1 * d1) + (d2 * d2 + d3 * d3))
                        + ((e0 * e0 + e1 * e1) + (e2 * e2 + e3 * e3));
#pragma unroll
                for (int o = 16; o; o >>= 1) s += __shfl_xor_sync(0xffffffffu, s, o);
                res = __float_as_uint(s);
            }
            if (lane == 0) ndb[w] = res;
        }
        __syncthreads();   // sync1: ndb ready; also orders skb reads before rewrites

        // ===== Phase B: warp 1 rank-sorts N_t into skb; warp 0 pre-picks u_{t+1},
        // loads its graph row, prefetches, publishes. No bar3, no merge here. =====
        const bool more = (t < EF - 1);
        if (w == 1) {
            u64 kb = ((u64)ndb[lane] << 32) | ((u64)(unsigned)(lane + 32) << 25)
                   | ((u64)(unsigned)nbid[par][lane] << 1);      // exp = 0
            int rank = warp_rank32(kb);
            skb[rank] = kb;
        } else if (w == 0 && more) {
            u64 kb = ((u64)ndb[lane] << 32) | ((u64)(unsigned)(lane + 32) << 25)
                   | ((u64)(unsigned)nbid[par][lane] << 1);
            // min-key unexpanded over (P_t ∪ N_t) always survives the merge
            u64 mk = u64min((ka & 1ull) ? ~0ull : ka, kb);
            u_reg = (int)((warp_min_key_lo(mk) >> 1) & 0x1FFFFu);
            int nb = __ldg(graph + (size_t)u_reg * RDEG + lane);  // L1/L2-hot
            {   // L1 storage prefetch; lead = rest of phase B + sync + dist start
                const float* rp = storage + (size_t)nb * DIMS;
#pragma unroll
                for (int i = 0; i < 8; i++) PF_L1(rp + i * 32);
            }
            // freshness reads before any visited write (vis is warp0-private)
            unsigned int word  = vis[nb >> 5];
            unsigned int fresh = ((word >> (nb & 31)) & 1u) ^ 1u;
            __syncwarp();
            nbid[par ^ 1][lane]   = nb;
            freshm[par ^ 1][lane] = fresh;
            atomicOr(&vis[nb >> 5], 1u << (nb & 31));
        }
        __syncthreads();   // sync2: publishes nbid/freshm/skb for the next phase A
    }

    // ---- final deferred merge of step EF-1, then output top-10 ----
    if (w == 0) {
        u64 lo = u64min(ka, skb[lane ^ 31]);
#pragma unroll
        for (int j = 16; j >= 1; j >>= 1) {
            u64 o = shfl_xor64(lo, j);
            lo = ((lane & j) == 0) ? u64min(lo, o) : u64max(lo, o);
        }
        // Tuple outputs flattened+concatenated: ids[B*K] then dists[B*K], float32.
        if (lane < KOUT) {
            out[b * KOUT + lane]             = (float)((lo >> 1) & 0x1FFFFu);
            out[BQ * KOUT + b * KOUT + lane] = __uint_as_float((unsigned int)(lo >> 32));
        }
    }
}

extern "C" void kernel_launch(void* const* d_in, const int* in_sizes, int n_in,
                              void* d_out, int out_size) {
    const float* query   = (const float*)d_in[0];
    const float* storage = (const float*)d_in[1];
    const int*   graph   = (const int*)d_in[2];
    const int*   initial = (const int*)d_in[3];
    (void)in_sizes; (void)n_in; (void)out_size;
    nsw_search_kernel<<<BQ, 1024>>>(query, storage, graph, initial, (float*)d_out);
}